// round 15
// baseline (speedup 1.0000x reference)
#include <cuda_runtime.h>
#include <cuda_fp16.h>
#include <cstdint>
#include <math.h>

#define NN 50000
#define NE 400000
#define DIN 256
#define EMB 256
#define NH 8
#define HD 32
#define SCAN_BLOCKS 196   // 196 * 256 = 50176 >= NN

// ---------------- scratch (device globals; no runtime alloc) ----------------
__device__ __align__(16) __half   g_Pih[(size_t)NN * EMB];   // projections, fp16
__device__ __align__(16) __half   g_Pjh[(size_t)NN * EMB];

// CSR
__device__ int g_cnt[NN];        // zero-initialized; scan1 re-zeroes after reading
__device__ int g_off[NN + 1];
__device__ int g_cursor[NN];
__device__ int g_psend[NE];      // sender of perm-ordered edge
__device__ int g_bsum[SCAN_BLOCKS];
__device__ int g_boff[SCAN_BLOCKS];

// fp16 operands for tensor-core GEMM (single term: Ah*Bh)
__device__ __align__(16) __half g_Ah[(size_t)NN * DIN];
__device__ __align__(16) __half g_Bh[(size_t)512 * DIN];   // [n_global][k]

// ---------------- helpers ----------------
__device__ __forceinline__ uint32_t smem_u32(const void* p) {
    uint32_t a;
    asm("{ .reg .u64 t; cvta.to.shared.u64 t, %1; cvt.u32.u64 %0, t; }" : "=r"(a) : "l"(p));
    return a;
}
__device__ __forceinline__ uint32_t sw128(uint32_t off) { return off ^ ((off >> 3) & 0x70); }

__device__ __forceinline__ void ldsm_x4(uint32_t* r, uint32_t addr) {
    asm volatile("ldmatrix.sync.aligned.m8n8.x4.shared.b16 {%0,%1,%2,%3}, [%4];"
                 : "=r"(r[0]), "=r"(r[1]), "=r"(r[2]), "=r"(r[3]) : "r"(addr));
}
__device__ __forceinline__ void mma16816(float* c, const uint32_t* a, const uint32_t* b) {
    asm volatile("mma.sync.aligned.m16n8k16.row.col.f32.f16.f16.f32 "
                 "{%0,%1,%2,%3}, {%4,%5,%6,%7}, {%8,%9}, {%0,%1,%2,%3};"
                 : "+f"(c[0]), "+f"(c[1]), "+f"(c[2]), "+f"(c[3])
                 : "r"(a[0]), "r"(a[1]), "r"(a[2]), "r"(a[3]), "r"(b[0]), "r"(b[1]));
}
__device__ __forceinline__ void cp_async16(uint32_t dst, const void* src) {
    asm volatile("cp.async.cg.shared.global [%0], [%1], 16;" :: "r"(dst), "l"(src));
}
#define CP_COMMIT() asm volatile("cp.async.commit_group;" ::: "memory")
#define CP_WAIT(n)  asm volatile("cp.async.wait_group %0;" :: "n"(n) : "memory")

__device__ __forceinline__ float frcp(float x) {
    float r;
    asm("rcp.approx.f32 %0, %1;" : "=f"(r) : "f"(x));
    return r;
}

// ---------------- convert nodes to fp16 ----------------
__global__ __launch_bounds__(256) void presplit_nodes(const float* __restrict__ nodes) {
    size_t i = (size_t)blockIdx.x * blockDim.x + threadIdx.x;   // unit of 8 floats
    size_t total = (size_t)NN * DIN / 8;
    if (i >= total) return;
    const float4* src = (const float4*)nodes + i * 2;
    float4 v0 = src[0], v1 = src[1];
    float f[8] = {v0.x, v0.y, v0.z, v0.w, v1.x, v1.y, v1.z, v1.w};
    alignas(16) __half h[8];
#pragma unroll
    for (int j = 0; j < 8; j++) h[j] = __float2half(f[j]);
    *(uint4*)(g_Ah + i * 8) = *(uint4*)h;
}

// ---------------- transpose W into [n][k] fp16 ----------------
__global__ __launch_bounds__(256) void presplit_W(const float* __restrict__ Wi,
                                                  const float* __restrict__ Wj) {
    int idx = blockIdx.x * blockDim.x + threadIdx.x;
    if (idx >= 512 * 256) return;
    int n = idx >> 8, k = idx & 255;
    const float* W = (n < 256) ? Wi : Wj;
    int col = n & 255;
    float x = W[(size_t)k * 256 + col];
    g_Bh[(size_t)n * 256 + k] = __float2half(x);
}

// ---------------- fp16 tensor-core GEMM, full upfront prefetch (4 stages) ---
__global__ __launch_bounds__(512) void gemm_mma(const float* __restrict__ bi,
                                                const float* __restrict__ bj) {
    extern __shared__ char dsm[];
    uint32_t base = (smem_u32(dsm) + 1023) & ~1023u;
    const uint32_t STG = 32768u;   // 2 x 16KB tiles per stage, 4 stages resident

    int tid = threadIdx.x, wid = tid >> 5, lane = tid & 31;
    int warp_m = wid & 3, warp_n = wid >> 2;
    int m_base = warp_m * 32, n_base = warp_n * 32;
    int ntile = blockIdx.x;
    int m0 = blockIdx.y * 128;
    size_t brow0 = (size_t)ntile * 128 * 256;

    float acc[2][4][4];
#pragma unroll
    for (int i = 0; i < 2; i++)
#pragma unroll
        for (int j = 0; j < 4; j++)
#pragma unroll
            for (int q = 0; q < 4; q++) acc[i][j][q] = 0.0f;

#define LOAD_STAGE(sbuf, kc_) do {                                         \
    uint32_t sA_ = (sbuf), sB_ = (sbuf) + 16384;                            \
    int k0_ = (kc_) * 64;                                                   \
    _Pragma("unroll")                                                       \
    for (int u = tid; u < 1024; u += 512) {                                 \
        int r_ = u >> 3, g_ = u & 7;                                        \
        uint32_t off_ = sw128((uint32_t)(r_ * 128 + g_ * 16));              \
        int row_ = m0 + r_; if (row_ > NN - 1) row_ = NN - 1;               \
        size_t sa_ = (size_t)row_ * 256 + k0_ + g_ * 8;                     \
        cp_async16(sA_ + off_, g_Ah + sa_);                                 \
        size_t sb_ = brow0 + (size_t)r_ * 256 + k0_ + g_ * 8;               \
        cp_async16(sB_ + off_, g_Bh + sb_);                                 \
    }                                                                       \
} while (0)

    // issue ALL four chunk loads upfront (one commit group each)
    LOAD_STAGE(base, 0);            CP_COMMIT();
    LOAD_STAGE(base + STG, 1);      CP_COMMIT();
    LOAD_STAGE(base + 2 * STG, 2);  CP_COMMIT();
    LOAD_STAGE(base + 3 * STG, 3);  CP_COMMIT();

#pragma unroll
    for (int kc = 0; kc < 4; kc++) {
        switch (kc) {
            case 0: CP_WAIT(3); break;
            case 1: CP_WAIT(2); break;
            case 2: CP_WAIT(1); break;
            default: CP_WAIT(0); break;
        }
        __syncthreads();
        uint32_t cur = base + (uint32_t)kc * STG;
        uint32_t sA = cur, sB = cur + 16384;
#pragma unroll
        for (int ks = 0; ks < 4; ks++) {
            uint32_t ah[2][4];
#pragma unroll
            for (int mi = 0; mi < 2; mi++) {
                uint32_t off = sw128((uint32_t)((m_base + mi * 16 + (lane & 15)) * 128 +
                                                ks * 32 + (lane >> 4) * 16));
                ldsm_x4(ah[mi], sA + off);
            }
            uint32_t bh[8];
#pragma unroll
            for (int np = 0; np < 2; np++) {
                int g = lane >> 3;
                int nrow = n_base + np * 16 + (lane & 7) + ((g & 2) ? 8 : 0);
                uint32_t off = sw128((uint32_t)(nrow * 128 + ks * 32 + (g & 1) * 16));
                ldsm_x4(&bh[np * 4], sB + off);
            }
#pragma unroll
            for (int mi = 0; mi < 2; mi++)
#pragma unroll
                for (int nb = 0; nb < 4; nb++) {
                    const int bo = (nb >> 1) * 4 + (nb & 1) * 2;
                    mma16816(acc[mi][nb], ah[mi], &bh[bo]);
                }
        }
    }

    __half* P = (ntile < 2) ? g_Pih : g_Pjh;
    const float* bias = (ntile < 2) ? bi : bj;
    int colbase = (ntile & 1) * 128;
#pragma unroll
    for (int mi = 0; mi < 2; mi++) {
        int mrow0 = m0 + m_base + mi * 16 + (lane >> 2);
#pragma unroll
        for (int nb = 0; nb < 4; nb++) {
            int n = n_base + nb * 8 + 2 * (lane & 3);
            float b0 = bias[colbase + n], b1 = bias[colbase + n + 1];
            if (mrow0 < NN) {
                __half2 v = __floats2half2_rn(acc[mi][nb][0] + b0, acc[mi][nb][1] + b1);
                *(__half2*)(P + (size_t)mrow0 * 256 + colbase + n) = v;
            }
            if (mrow0 + 8 < NN) {
                __half2 v = __floats2half2_rn(acc[mi][nb][2] + b0, acc[mi][nb][3] + b1);
                *(__half2*)(P + (size_t)(mrow0 + 8) * 256 + colbase + n) = v;
            }
        }
    }
#undef LOAD_STAGE
}

// ---------------- CSR build ----------------
__global__ void hist_kernel(const int* __restrict__ receivers) {
    int e = blockIdx.x * blockDim.x + threadIdx.x;
    if (e < NE) atomicAdd(&g_cnt[receivers[e]], 1);
}

__global__ __launch_bounds__(256) void scan1_kernel() {
    int t = threadIdx.x, b = blockIdx.x;
    int idx = b * 256 + t;
    int lane = t & 31, w = t >> 5;
    int v = 0;
    if (idx < NN) {
        v = g_cnt[idx];
        g_cnt[idx] = 0;   // self-restore for next graph replay
    }
    int x = v;
#pragma unroll
    for (int o = 1; o < 32; o <<= 1) {
        int y = __shfl_up_sync(0xffffffffu, x, o);
        if (lane >= o) x += y;
    }
    __shared__ int ws[8];
    if (lane == 31) ws[w] = x;
    __syncthreads();
    if (t < 8) {
        int y = ws[t];
        int z = y;
#pragma unroll
        for (int o = 1; o < 8; o <<= 1) {
            int q = __shfl_up_sync(0xffu, z, o);
            if (t >= o) z += q;
        }
        ws[t] = z - y;
    }
    __syncthreads();
    int excl = x - v + ws[w];
    if (idx < NN) g_off[idx] = excl;
    if (t == 255) g_bsum[b] = excl + v;
}

__global__ __launch_bounds__(256) void scan2_kernel() {
    int t = threadIdx.x;
    int lane = t & 31, w = t >> 5;
    int v = (t < SCAN_BLOCKS) ? g_bsum[t] : 0;
    int x = v;
#pragma unroll
    for (int o = 1; o < 32; o <<= 1) {
        int y = __shfl_up_sync(0xffffffffu, x, o);
        if (lane >= o) x += y;
    }
    __shared__ int ws[8];
    if (lane == 31) ws[w] = x;
    __syncthreads();
    if (t < 8) {
        int y = ws[t];
        int z = y;
#pragma unroll
        for (int o = 1; o < 8; o <<= 1) {
            int q = __shfl_up_sync(0xffu, z, o);
            if (t >= o) z += q;
        }
        ws[t] = z - y;
    }
    __syncthreads();
    if (t < SCAN_BLOCKS) g_boff[t] = x - v + ws[w];
}

__global__ __launch_bounds__(256) void scan3_kernel() {
    int t = threadIdx.x, b = blockIdx.x;
    int idx = b * 256 + t;
    if (idx < NN) {
        int o = g_off[idx] + g_boff[b];
        g_off[idx] = o;
        g_cursor[idx] = o;
    }
    if (idx == 0) g_off[NN] = NE;
}

__global__ void scatter_kernel(const int* __restrict__ senders,
                               const int* __restrict__ receivers) {
    int e = blockIdx.x * blockDim.x + threadIdx.x;
    if (e >= NE) return;
    int r = receivers[e];
    int pos = atomicAdd(&g_cursor[r], 1);
    g_psend[pos] = senders[e];
}

// ---------------- fused edge phase: warp per receiver, SINGLE PASS ----------
// fp16 rows: lane owns 8 consecutive cols. head = lane>>2; reduce = 2 shfl.
// Online softmax. mish via quad-grouped reciprocal: 2 RCP per 8 elements.
__global__ __launch_bounds__(256) void fused_edge_kernel(
    const float* __restrict__ a_w, float* __restrict__ out)
{
    int lane = threadIdx.x & 31;
    int r = blockIdx.x * 8 + (threadIdx.x >> 5);
    if (r >= NN) return;
    int lo = g_off[r];
    int deg = g_off[r + 1] - lo;

    float acc[8];
#pragma unroll
    for (int q = 0; q < 8; q++) acc[q] = 0.0f;
    float m = -INFINITY, s = 0.0f;

    if (deg > 0) {
        float aw[8];
        {
            const float4* a4 = (const float4*)(a_w + (lane & 3) * 8);
            float4 w0 = a4[0], w1 = a4[1];
            aw[0] = w0.x; aw[1] = w0.y; aw[2] = w0.z; aw[3] = w0.w;
            aw[4] = w1.x; aw[5] = w1.y; aw[6] = w1.z; aw[7] = w1.w;
        }
        float pj[8];
        {
            uint4 u = *(const uint4*)(g_Pjh + (size_t)r * 256 + lane * 8);
            const __half2* h2 = (const __half2*)&u;
#pragma unroll
            for (int c = 0; c < 4; c++) {
                float2 f = __half22float2(h2[c]);
                pj[c * 2] = f.x; pj[c * 2 + 1] = f.y;
            }
        }
        const int* ps = g_psend + lo;

        uint4 u = *(const uint4*)(g_Pih + (size_t)ps[0] * 256 + lane * 8);
        for (int j = 0; j < deg; j++) {
            // prefetch next edge's row before the dependent math chain
            uint4 un = *(const uint4*)(
                g_Pih + (size_t)ps[(j + 1 < deg) ? j + 1 : j] * 256 + lane * 8);

            const __half2* h2 = (const __half2*)&u;
            float f[8];
#pragma unroll
            for (int c = 0; c < 4; c++) {
                float2 t = __half22float2(h2[c]);
                f[c * 2] = t.x; f[c * 2 + 1] = t.y;
            }

            // mish(x)*aw summed, with quad-grouped reciprocals.
            // x clamped at 10 inside exp: tanh factor error < 4e-9 there.
            float uu[8], dd[8], xa[8];
#pragma unroll
            for (int c = 0; c < 8; c++) {
                float x = f[c] + pj[c];
                float t = __expf(fminf(x, 10.0f));
                uu[c] = fmaf(t, t, t + t);       // t^2 + 2t
                dd[c] = uu[c] + 2.0f;
                xa[c] = x * aw[c];
            }
            float p = 0.0f;
#pragma unroll
            for (int q = 0; q < 8; q += 4) {
                float d01 = dd[q] * dd[q + 1];
                float d23 = dd[q + 2] * dd[q + 3];
                float rr = frcp(d01 * d23);
                float i01 = d23 * rr;            // 1/(d0*d1)
                float i23 = d01 * rr;            // 1/(d2*d3)
                p = fmaf(xa[q] * uu[q], dd[q + 1] * i01, p);
                p = fmaf(xa[q + 1] * uu[q + 1], dd[q] * i01, p);
                p = fmaf(xa[q + 2] * uu[q + 2], dd[q + 3] * i23, p);
                p = fmaf(xa[q + 3] * uu[q + 3], dd[q + 2] * i23, p);
            }
            p += __shfl_xor_sync(0xffffffffu, p, 1);
            p += __shfl_xor_sync(0xffffffffu, p, 2);

            // online softmax update (uniform across the 4-lane head group)
            if (p > m) {
                float sc = __expf(m - p);
                s *= sc;
#pragma unroll
                for (int c = 0; c < 8; c++) acc[c] *= sc;
                m = p;
            }
            float w = __expf(p - m);
            s += w;
#pragma unroll
            for (int c = 0; c < 8; c++) acc[c] = fmaf(f[c], w, acc[c]);

            u = un;
        }
        float dinv = frcp(s);
#pragma unroll
        for (int c = 0; c < 8; c++) acc[c] *= dinv;
    }

    float4* o4 = (float4*)(out + (size_t)r * 256 + lane * 8);
    o4[0] = make_float4(acc[0], acc[1], acc[2], acc[3]);
    o4[1] = make_float4(acc[4], acc[5], acc[6], acc[7]);
}

// ---------------- launch ----------------
extern "C" void kernel_launch(void* const* d_in, const int* in_sizes, int n_in,
                              void* d_out, int out_size)
{
    const float* nodes     = (const float*)d_in[0];
    const int*   senders   = (const int*)d_in[1];
    const int*   receivers = (const int*)d_in[2];
    const float* Wi        = (const float*)d_in[3];
    const float* bi        = (const float*)d_in[4];
    const float* Wj        = (const float*)d_in[5];
    const float* bj        = (const float*)d_in[6];
    const float* a_w       = (const float*)d_in[7];
    float* out = (float*)d_out;

    static cudaStream_t s2 = nullptr;
    static cudaEvent_t evF = nullptr, evJ = nullptr, evW = nullptr;
    if (!s2) {
        cudaFuncSetAttribute(gemm_mma, cudaFuncAttributeMaxDynamicSharedMemorySize, 132096);
        cudaStreamCreateWithFlags(&s2, cudaStreamNonBlocking);
        cudaEventCreateWithFlags(&evF, cudaEventDisableTiming);
        cudaEventCreateWithFlags(&evJ, cudaEventDisableTiming);
        cudaEventCreateWithFlags(&evW, cudaEventDisableTiming);
    }

    // fork: W conversion + CSR build on side stream
    cudaEventRecord(evF, 0);
    cudaStreamWaitEvent(s2, evF, 0);
    presplit_W<<<(512 * 256 + 255) / 256, 256, 0, s2>>>(Wi, Wj);
    cudaEventRecord(evW, s2);
    hist_kernel<<<(NE + 255) / 256, 256, 0, s2>>>(receivers);
    scan1_kernel<<<SCAN_BLOCKS, 256, 0, s2>>>();
    scan2_kernel<<<1, 256, 0, s2>>>();
    scan3_kernel<<<SCAN_BLOCKS, 256, 0, s2>>>();
    scatter_kernel<<<(NE + 255) / 256, 256, 0, s2>>>(senders, receivers);
    cudaEventRecord(evJ, s2);

    // main stream: node conversion, then GEMM (waits for W)
    presplit_nodes<<<(NN * DIN / 8 + 255) / 256, 256>>>(nodes);
    cudaStreamWaitEvent(0, evW, 0);

    dim3 gg(4, (NN + 127) / 128);
    gemm_mma<<<gg, 512, 132096>>>(bi, bj);

    // join, then fused edge phase
    cudaStreamWaitEvent(0, evJ, 0);
    fused_edge_kernel<<<(NN + 7) / 8, 256>>>(a_w, out);
}

// round 16
// speedup vs baseline: 1.0296x; 1.0296x over previous
#include <cuda_runtime.h>
#include <cuda_fp16.h>
#include <cstdint>
#include <math.h>

#define NN 50000
#define NE 400000
#define DIN 256
#define EMB 256
#define NH 8
#define HD 32
#define SCAN_BLOCKS 196   // 196 * 256 = 50176 >= NN

// ---------------- scratch (device globals; no runtime alloc) ----------------
__device__ __align__(16) __half   g_Pih[(size_t)NN * EMB];   // projections, fp16
__device__ __align__(16) __half   g_Pjh[(size_t)NN * EMB];

// CSR
__device__ int g_cnt[NN];        // zero-initialized; scan1 re-zeroes after reading
__device__ int g_off[NN + 1];
__device__ int g_cursor[NN];
__device__ int g_psend[NE];      // sender of perm-ordered edge
__device__ int g_bsum[SCAN_BLOCKS];
__device__ int g_boff[SCAN_BLOCKS];

// fp16 operands for tensor-core GEMM (single term: Ah*Bh)
__device__ __align__(16) __half g_Ah[(size_t)NN * DIN];
__device__ __align__(16) __half g_Bh[(size_t)512 * DIN];   // [n_global][k]

// ---------------- helpers ----------------
__device__ __forceinline__ uint32_t smem_u32(const void* p) {
    uint32_t a;
    asm("{ .reg .u64 t; cvta.to.shared.u64 t, %1; cvt.u32.u64 %0, t; }" : "=r"(a) : "l"(p));
    return a;
}
__device__ __forceinline__ uint32_t sw128(uint32_t off) { return off ^ ((off >> 3) & 0x70); }

__device__ __forceinline__ void ldsm_x4(uint32_t* r, uint32_t addr) {
    asm volatile("ldmatrix.sync.aligned.m8n8.x4.shared.b16 {%0,%1,%2,%3}, [%4];"
                 : "=r"(r[0]), "=r"(r[1]), "=r"(r[2]), "=r"(r[3]) : "r"(addr));
}
__device__ __forceinline__ void mma16816(float* c, const uint32_t* a, const uint32_t* b) {
    asm volatile("mma.sync.aligned.m16n8k16.row.col.f32.f16.f16.f32 "
                 "{%0,%1,%2,%3}, {%4,%5,%6,%7}, {%8,%9}, {%0,%1,%2,%3};"
                 : "+f"(c[0]), "+f"(c[1]), "+f"(c[2]), "+f"(c[3])
                 : "r"(a[0]), "r"(a[1]), "r"(a[2]), "r"(a[3]), "r"(b[0]), "r"(b[1]));
}
__device__ __forceinline__ void cp_async16(uint32_t dst, const void* src) {
    asm volatile("cp.async.cg.shared.global [%0], [%1], 16;" :: "r"(dst), "l"(src));
}
#define CP_COMMIT() asm volatile("cp.async.commit_group;" ::: "memory")
#define CP_WAIT(n)  asm volatile("cp.async.wait_group %0;" :: "n"(n) : "memory")

__device__ __forceinline__ float frcp(float x) {
    float r;
    asm("rcp.approx.f32 %0, %1;" : "=f"(r) : "f"(x));
    return r;
}

// ---------------- convert nodes to fp16 ----------------
__global__ __launch_bounds__(256) void presplit_nodes(const float* __restrict__ nodes) {
    size_t i = (size_t)blockIdx.x * blockDim.x + threadIdx.x;   // unit of 8 floats
    size_t total = (size_t)NN * DIN / 8;
    if (i >= total) return;
    const float4* src = (const float4*)nodes + i * 2;
    float4 v0 = src[0], v1 = src[1];
    float f[8] = {v0.x, v0.y, v0.z, v0.w, v1.x, v1.y, v1.z, v1.w};
    alignas(16) __half h[8];
#pragma unroll
    for (int j = 0; j < 8; j++) h[j] = __float2half(f[j]);
    *(uint4*)(g_Ah + i * 8) = *(uint4*)h;
}

// ---------------- transpose W into [n][k] fp16 ----------------
__global__ __launch_bounds__(256) void presplit_W(const float* __restrict__ Wi,
                                                  const float* __restrict__ Wj) {
    int idx = blockIdx.x * blockDim.x + threadIdx.x;
    if (idx >= 512 * 256) return;
    int n = idx >> 8, k = idx & 255;
    const float* W = (n < 256) ? Wi : Wj;
    int col = n & 255;
    float x = W[(size_t)k * 256 + col];
    g_Bh[(size_t)n * 256 + k] = __float2half(x);
}

// ---------------- fp16 tensor-core GEMM, full upfront prefetch (4 stages) ---
__global__ __launch_bounds__(512) void gemm_mma(const float* __restrict__ bi,
                                                const float* __restrict__ bj) {
    extern __shared__ char dsm[];
    uint32_t base = (smem_u32(dsm) + 1023) & ~1023u;
    const uint32_t STG = 32768u;   // 2 x 16KB tiles per stage, 4 stages resident

    int tid = threadIdx.x, wid = tid >> 5, lane = tid & 31;
    int warp_m = wid & 3, warp_n = wid >> 2;
    int m_base = warp_m * 32, n_base = warp_n * 32;
    int ntile = blockIdx.x;
    int m0 = blockIdx.y * 128;
    size_t brow0 = (size_t)ntile * 128 * 256;

    float acc[2][4][4];
#pragma unroll
    for (int i = 0; i < 2; i++)
#pragma unroll
        for (int j = 0; j < 4; j++)
#pragma unroll
            for (int q = 0; q < 4; q++) acc[i][j][q] = 0.0f;

#define LOAD_STAGE(sbuf, kc_) do {                                         \
    uint32_t sA_ = (sbuf), sB_ = (sbuf) + 16384;                            \
    int k0_ = (kc_) * 64;                                                   \
    _Pragma("unroll")                                                       \
    for (int u = tid; u < 1024; u += 512) {                                 \
        int r_ = u >> 3, g_ = u & 7;                                        \
        uint32_t off_ = sw128((uint32_t)(r_ * 128 + g_ * 16));              \
        int row_ = m0 + r_; if (row_ > NN - 1) row_ = NN - 1;               \
        size_t sa_ = (size_t)row_ * 256 + k0_ + g_ * 8;                     \
        cp_async16(sA_ + off_, g_Ah + sa_);                                 \
        size_t sb_ = brow0 + (size_t)r_ * 256 + k0_ + g_ * 8;               \
        cp_async16(sB_ + off_, g_Bh + sb_);                                 \
    }                                                                       \
} while (0)

    LOAD_STAGE(base, 0);            CP_COMMIT();
    LOAD_STAGE(base + STG, 1);      CP_COMMIT();
    LOAD_STAGE(base + 2 * STG, 2);  CP_COMMIT();
    LOAD_STAGE(base + 3 * STG, 3);  CP_COMMIT();

#pragma unroll
    for (int kc = 0; kc < 4; kc++) {
        switch (kc) {
            case 0: CP_WAIT(3); break;
            case 1: CP_WAIT(2); break;
            case 2: CP_WAIT(1); break;
            default: CP_WAIT(0); break;
        }
        __syncthreads();
        uint32_t cur = base + (uint32_t)kc * STG;
        uint32_t sA = cur, sB = cur + 16384;
#pragma unroll
        for (int ks = 0; ks < 4; ks++) {
            uint32_t ah[2][4];
#pragma unroll
            for (int mi = 0; mi < 2; mi++) {
                uint32_t off = sw128((uint32_t)((m_base + mi * 16 + (lane & 15)) * 128 +
                                                ks * 32 + (lane >> 4) * 16));
                ldsm_x4(ah[mi], sA + off);
            }
            uint32_t bh[8];
#pragma unroll
            for (int np = 0; np < 2; np++) {
                int g = lane >> 3;
                int nrow = n_base + np * 16 + (lane & 7) + ((g & 2) ? 8 : 0);
                uint32_t off = sw128((uint32_t)(nrow * 128 + ks * 32 + (g & 1) * 16));
                ldsm_x4(&bh[np * 4], sB + off);
            }
#pragma unroll
            for (int mi = 0; mi < 2; mi++)
#pragma unroll
                for (int nb = 0; nb < 4; nb++) {
                    const int bo = (nb >> 1) * 4 + (nb & 1) * 2;
                    mma16816(acc[mi][nb], ah[mi], &bh[bo]);
                }
        }
    }

    __half* P = (ntile < 2) ? g_Pih : g_Pjh;
    const float* bias = (ntile < 2) ? bi : bj;
    int colbase = (ntile & 1) * 128;
#pragma unroll
    for (int mi = 0; mi < 2; mi++) {
        int mrow0 = m0 + m_base + mi * 16 + (lane >> 2);
#pragma unroll
        for (int nb = 0; nb < 4; nb++) {
            int n = n_base + nb * 8 + 2 * (lane & 3);
            float b0 = bias[colbase + n], b1 = bias[colbase + n + 1];
            if (mrow0 < NN) {
                __half2 v = __floats2half2_rn(acc[mi][nb][0] + b0, acc[mi][nb][1] + b1);
                *(__half2*)(P + (size_t)mrow0 * 256 + colbase + n) = v;
            }
            if (mrow0 + 8 < NN) {
                __half2 v = __floats2half2_rn(acc[mi][nb][2] + b0, acc[mi][nb][3] + b1);
                *(__half2*)(P + (size_t)(mrow0 + 8) * 256 + colbase + n) = v;
            }
        }
    }
#undef LOAD_STAGE
}

// ---------------- CSR build ----------------
__global__ void hist_kernel(const int* __restrict__ receivers) {
    int e = blockIdx.x * blockDim.x + threadIdx.x;
    if (e < NE) atomicAdd(&g_cnt[receivers[e]], 1);
}

__global__ __launch_bounds__(256) void scan1_kernel() {
    int t = threadIdx.x, b = blockIdx.x;
    int idx = b * 256 + t;
    int lane = t & 31, w = t >> 5;
    int v = 0;
    if (idx < NN) {
        v = g_cnt[idx];
        g_cnt[idx] = 0;   // self-restore for next graph replay
    }
    int x = v;
#pragma unroll
    for (int o = 1; o < 32; o <<= 1) {
        int y = __shfl_up_sync(0xffffffffu, x, o);
        if (lane >= o) x += y;
    }
    __shared__ int ws[8];
    if (lane == 31) ws[w] = x;
    __syncthreads();
    if (t < 8) {
        int y = ws[t];
        int z = y;
#pragma unroll
        for (int o = 1; o < 8; o <<= 1) {
            int q = __shfl_up_sync(0xffu, z, o);
            if (t >= o) z += q;
        }
        ws[t] = z - y;
    }
    __syncthreads();
    int excl = x - v + ws[w];
    if (idx < NN) g_off[idx] = excl;
    if (t == 255) g_bsum[b] = excl + v;
}

__global__ __launch_bounds__(256) void scan2_kernel() {
    int t = threadIdx.x;
    int lane = t & 31, w = t >> 5;
    int v = (t < SCAN_BLOCKS) ? g_bsum[t] : 0;
    int x = v;
#pragma unroll
    for (int o = 1; o < 32; o <<= 1) {
        int y = __shfl_up_sync(0xffffffffu, x, o);
        if (lane >= o) x += y;
    }
    __shared__ int ws[8];
    if (lane == 31) ws[w] = x;
    __syncthreads();
    if (t < 8) {
        int y = ws[t];
        int z = y;
#pragma unroll
        for (int o = 1; o < 8; o <<= 1) {
            int q = __shfl_up_sync(0xffu, z, o);
            if (t >= o) z += q;
        }
        ws[t] = z - y;
    }
    __syncthreads();
    if (t < SCAN_BLOCKS) g_boff[t] = x - v + ws[w];
}

__global__ __launch_bounds__(256) void scan3_kernel() {
    int t = threadIdx.x, b = blockIdx.x;
    int idx = b * 256 + t;
    if (idx < NN) {
        int o = g_off[idx] + g_boff[b];
        g_off[idx] = o;
        g_cursor[idx] = o;
    }
    if (idx == 0) g_off[NN] = NE;
}

__global__ void scatter_kernel(const int* __restrict__ senders,
                               const int* __restrict__ receivers) {
    int e = blockIdx.x * blockDim.x + threadIdx.x;
    if (e >= NE) return;
    int r = receivers[e];
    int pos = atomicAdd(&g_cursor[r], 1);
    g_psend[pos] = senders[e];
}

// ---------------- fused edge phase: warp per receiver, SINGLE PASS ----------
// fp16 rows: lane owns 8 consecutive cols. head = lane>>2; reduce = 2 shfl.
// Online softmax. mish via d-form: mish(x)*a = x*a - 2*x*a/d, d = t(t+2)+2.
// Quad-scoped temporaries + launch_bounds(256,4) for higher occupancy.
__global__ __launch_bounds__(256, 4) void fused_edge_kernel(
    const float* __restrict__ a_w, float* __restrict__ out)
{
    int lane = threadIdx.x & 31;
    int r = blockIdx.x * 8 + (threadIdx.x >> 5);
    if (r >= NN) return;
    int lo = g_off[r];
    int deg = g_off[r + 1] - lo;

    float acc[8];
#pragma unroll
    for (int q = 0; q < 8; q++) acc[q] = 0.0f;
    float m = -INFINITY, s = 0.0f;

    if (deg > 0) {
        float aw[8];
        {
            const float4* a4 = (const float4*)(a_w + (lane & 3) * 8);
            float4 w0 = a4[0], w1 = a4[1];
            aw[0] = w0.x; aw[1] = w0.y; aw[2] = w0.z; aw[3] = w0.w;
            aw[4] = w1.x; aw[5] = w1.y; aw[6] = w1.z; aw[7] = w1.w;
        }
        float pj[8];
        {
            uint4 u = *(const uint4*)(g_Pjh + (size_t)r * 256 + lane * 8);
            const __half2* h2 = (const __half2*)&u;
#pragma unroll
            for (int c = 0; c < 4; c++) {
                float2 f = __half22float2(h2[c]);
                pj[c * 2] = f.x; pj[c * 2 + 1] = f.y;
            }
        }
        const int* ps = g_psend + lo;

        uint4 u = *(const uint4*)(g_Pih + (size_t)ps[0] * 256 + lane * 8);
        for (int j = 0; j < deg; j++) {
            // prefetch next edge's row before the dependent math chain
            uint4 un = *(const uint4*)(
                g_Pih + (size_t)ps[(j + 1 < deg) ? j + 1 : j] * 256 + lane * 8);

            const __half2* h2 = (const __half2*)&u;
            float f[8];
#pragma unroll
            for (int c = 0; c < 4; c++) {
                float2 t = __half22float2(h2[c]);
                f[c * 2] = t.x; f[c * 2 + 1] = t.y;
            }

            // p = sum xa - 2*sum xa/d;  d = t^2+2t+2, t = e^min(x,10)
            float p0 = 0.0f, pd = 0.0f;
#pragma unroll
            for (int q = 0; q < 8; q += 4) {
                float d[4], xa[4];
#pragma unroll
                for (int c = 0; c < 4; c++) {
                    float x = f[q + c] + pj[q + c];
                    float t = __expf(fminf(x, 10.0f));
                    d[c] = fmaf(t, t + 2.0f, 2.0f);
                    xa[c] = x * aw[q + c];
                    p0 += xa[c];
                }
                float d01 = d[0] * d[1];
                float d23 = d[2] * d[3];
                float rr = frcp(d01 * d23);
                float i01 = d23 * rr;            // 1/(d0*d1)
                float i23 = d01 * rr;            // 1/(d2*d3)
                pd = fmaf(xa[0], d[1] * i01, pd);
                pd = fmaf(xa[1], d[0] * i01, pd);
                pd = fmaf(xa[2], d[3] * i23, pd);
                pd = fmaf(xa[3], d[2] * i23, pd);
            }
            float p = fmaf(-2.0f, pd, p0);
            p += __shfl_xor_sync(0xffffffffu, p, 1);
            p += __shfl_xor_sync(0xffffffffu, p, 2);

            // online softmax update (uniform across the 4-lane head group)
            if (p > m) {
                float sc = __expf(m - p);
                s *= sc;
#pragma unroll
                for (int c = 0; c < 8; c++) acc[c] *= sc;
                m = p;
            }
            float w = __expf(p - m);
            s += w;
#pragma unroll
            for (int c = 0; c < 8; c++) acc[c] = fmaf(f[c], w, acc[c]);

            u = un;
        }
        float dinv = frcp(s);
#pragma unroll
        for (int c = 0; c < 8; c++) acc[c] *= dinv;
    }

    float4* o4 = (float4*)(out + (size_t)r * 256 + lane * 8);
    o4[0] = make_float4(acc[0], acc[1], acc[2], acc[3]);
    o4[1] = make_float4(acc[4], acc[5], acc[6], acc[7]);
}

// ---------------- launch ----------------
extern "C" void kernel_launch(void* const* d_in, const int* in_sizes, int n_in,
                              void* d_out, int out_size)
{
    const float* nodes     = (const float*)d_in[0];
    const int*   senders   = (const int*)d_in[1];
    const int*   receivers = (const int*)d_in[2];
    const float* Wi        = (const float*)d_in[3];
    const float* bi        = (const float*)d_in[4];
    const float* Wj        = (const float*)d_in[5];
    const float* bj        = (const float*)d_in[6];
    const float* a_w       = (const float*)d_in[7];
    float* out = (float*)d_out;

    static cudaStream_t s2 = nullptr;
    static cudaEvent_t evF = nullptr, evJ = nullptr, evW = nullptr;
    if (!s2) {
        cudaFuncSetAttribute(gemm_mma, cudaFuncAttributeMaxDynamicSharedMemorySize, 132096);
        cudaStreamCreateWithFlags(&s2, cudaStreamNonBlocking);
        cudaEventCreateWithFlags(&evF, cudaEventDisableTiming);
        cudaEventCreateWithFlags(&evJ, cudaEventDisableTiming);
        cudaEventCreateWithFlags(&evW, cudaEventDisableTiming);
    }

    // fork: W conversion + CSR build on side stream
    cudaEventRecord(evF, 0);
    cudaStreamWaitEvent(s2, evF, 0);
    presplit_W<<<(512 * 256 + 255) / 256, 256, 0, s2>>>(Wi, Wj);
    cudaEventRecord(evW, s2);
    hist_kernel<<<(NE + 255) / 256, 256, 0, s2>>>(receivers);
    scan1_kernel<<<SCAN_BLOCKS, 256, 0, s2>>>();
    scan2_kernel<<<1, 256, 0, s2>>>();
    scan3_kernel<<<SCAN_BLOCKS, 256, 0, s2>>>();
    scatter_kernel<<<(NE + 255) / 256, 256, 0, s2>>>(senders, receivers);
    cudaEventRecord(evJ, s2);

    // main stream: node conversion, then GEMM (waits for W)
    presplit_nodes<<<(NN * DIN / 8 + 255) / 256, 256>>>(nodes);
    cudaStreamWaitEvent(0, evW, 0);

    dim3 gg(4, (NN + 127) / 128);
    gemm_mma<<<gg, 512, 132096>>>(bi, bj);

    // join, then fused edge phase
    cudaStreamWaitEvent(0, evJ, 0);
    fused_edge_kernel<<<(NN + 7) / 8, 256>>>(a_w, out);
}